// round 1
// baseline (speedup 1.0000x reference)
#include <cuda_runtime.h>
#include <math.h>

#define BATCH     32768
#define IN_DIM    64
#define NUM_BINS  10
#define EMBED_DIM 64
#define NPART     256
#define NTHRESH   9   // bins[0..8] thresholds (clip to 9 is automatic)

// ---- scratch (device globals; no allocation allowed) ----
__device__ float g_pmin[NPART * IN_DIM];
__device__ float g_pmax[NPART * IN_DIM];
__device__ float g_mn[IN_DIM];
__device__ float g_dn[IN_DIM];
__device__ float g_bins[NUM_BINS];
__device__ float g_M[NUM_BINS * EMBED_DIM];   // M[k][f] = embed[k] . W[f]

// ================= Kernel 1: per-column partial min/max =================
__global__ void k_minmax(const float* __restrict__ x) {
    const int c    = threadIdx.x & 63;         // column
    const int rsub = threadIdx.x >> 6;         // 0..3 (4 rows per block-iter)
    const int rowsPerIter = gridDim.x * 4;

    float mn =  INFINITY, mx = -INFINITY;
    for (int row = blockIdx.x * 4 + rsub; row < BATCH; row += rowsPerIter) {
        float v = x[row * IN_DIM + c];
        mn = fminf(mn, v);
        mx = fmaxf(mx, v);
    }
    __shared__ float smn[256], smx[256];
    smn[threadIdx.x] = mn;
    smx[threadIdx.x] = mx;
    __syncthreads();
    if (threadIdx.x < 64) {
        float a = fminf(fminf(smn[c], smn[c + 64]), fminf(smn[c + 128], smn[c + 192]));
        float b = fmaxf(fmaxf(smx[c], smx[c + 64]), fmaxf(smx[c + 128], smx[c + 192]));
        g_pmin[blockIdx.x * IN_DIM + c] = a;
        g_pmax[blockIdx.x * IN_DIM + c] = b;
    }
}

// ====== Kernel 2: finalize min/max, bins = cumsum(softmax), M = embed@W^T ======
__global__ void k_small(const float* __restrict__ logits,
                        const float* __restrict__ embed,
                        const float* __restrict__ W) {
    const int tid = threadIdx.x;

    // bins: replicate reference f32 op sequence as closely as possible.
    // exp computed via double then rounded -> correctly-rounded f32, immune
    // to --use_fast_math's __expf substitution.
    if (tid == 0) {
        float l[NUM_BINS];
        float m = -INFINITY;
        #pragma unroll
        for (int i = 0; i < NUM_BINS; i++) { l[i] = logits[i]; m = fmaxf(m, l[i]); }
        float e[NUM_BINS];
        float s = 0.f;
        #pragma unroll
        for (int i = 0; i < NUM_BINS; i++) {
            e[i] = (float)exp((double)(l[i] - m));
            s += e[i];
        }
        float cum = 0.f;
        #pragma unroll
        for (int i = 0; i < NUM_BINS; i++) {
            cum += __fdiv_rn(e[i], s);       // IEEE division even under fast-math
            g_bins[i] = cum;
        }
    }

    // finalize per-column min / denom
    if (tid < IN_DIM) {
        float mn =  INFINITY, mx = -INFINITY;
        for (int i = 0; i < NPART; i++) {
            mn = fminf(mn, g_pmin[i * IN_DIM + tid]);
            mx = fmaxf(mx, g_pmax[i * IN_DIM + tid]);
        }
        g_mn[tid] = mn;
        g_dn[tid] = (mx - mn) + 1e-6f;
    }

    // M[k][f] = sum_e embed[k][e] * W[f][e]   (10 x 64, 640 threads)
    if (tid < NUM_BINS * EMBED_DIM) {
        const int k = tid / EMBED_DIM;
        const int f = tid % EMBED_DIM;
        const float* er = embed + k * EMBED_DIM;
        const float* wr = W + f * EMBED_DIM;
        float s = 0.f;
        #pragma unroll 8
        for (int e2 = 0; e2 < EMBED_DIM; e2++) s = fmaf(er[e2], wr[e2], s);
        g_M[tid] = s;
    }
}

// ================= Kernel 3: main (one warp per row) =================
// out[b,f] = 64*(M[0][f] + bias[f]) + sum_{k=1..9} c_k * (M[k][f]-M[k-1][f])
// c_k = #{n in 0..63 : bins[k-1] < xn(b,n)}  via warp ballots.
__global__ void __launch_bounds__(256) k_main(const float* __restrict__ x,
                                              const float* __restrict__ bias,
                                              float* __restrict__ out) {
    const int lane   = threadIdx.x & 31;
    const int warp   = (blockIdx.x * blockDim.x + threadIdx.x) >> 5;
    const int nwarps = (gridDim.x * blockDim.x) >> 5;

    const int c0 = lane * 2;
    const int c1 = lane * 2 + 1;

    const float mn0 = g_mn[c0], mn1 = g_mn[c1];
    const float dn0 = g_dn[c0], dn1 = g_dn[c1];

    float bins[NTHRESH];
    #pragma unroll
    for (int k = 0; k < NTHRESH; k++) bins[k] = g_bins[k];

    const float base0 = 64.f * (g_M[c0] + bias[c0]);
    const float base1 = 64.f * (g_M[c1] + bias[c1]);

    float D0[NTHRESH], D1[NTHRESH];
    #pragma unroll
    for (int k = 0; k < NTHRESH; k++) {
        D0[k] = g_M[(k + 1) * EMBED_DIM + c0] - g_M[k * EMBED_DIM + c0];
        D1[k] = g_M[(k + 1) * EMBED_DIM + c1] - g_M[k * EMBED_DIM + c1];
    }

    const float2* __restrict__ x2   = (const float2*)x;
    float2* __restrict__       out2 = (float2*)out;

    for (int row = warp; row < BATCH; row += nwarps) {
        float2 xv = x2[row * 32 + lane];
        // exact same f32 op sequence as the reference: sub then IEEE divide
        float xn0 = __fdiv_rn(xv.x - mn0, dn0);
        float xn1 = __fdiv_rn(xv.y - mn1, dn1);

        float a0 = base0, a1 = base1;
        #pragma unroll
        for (int k = 0; k < NTHRESH; k++) {
            unsigned m0 = __ballot_sync(0xffffffffu, xn0 > bins[k]);
            unsigned m1 = __ballot_sync(0xffffffffu, xn1 > bins[k]);
            float fc = (float)(__popc(m0) + __popc(m1));
            a0 = fmaf(fc, D0[k], a0);
            a1 = fmaf(fc, D1[k], a1);
        }
        out2[row * 32 + lane] = make_float2(a0, a1);
    }
}

extern "C" void kernel_launch(void* const* d_in, const int* in_sizes, int n_in,
                              void* d_out, int out_size) {
    const float* x      = (const float*)d_in[0];
    const float* logits = (const float*)d_in[1];
    const float* embed  = (const float*)d_in[2];
    const float* W      = (const float*)d_in[3];
    const float* bias   = (const float*)d_in[4];
    float* out          = (float*)d_out;

    k_minmax<<<NPART, 256>>>(x);
    k_small<<<1, 640>>>(logits, embed, W);
    k_main<<<512, 256>>>(x, bias, out);
}